// round 9
// baseline (speedup 1.0000x reference)
#include <cuda_runtime.h>
#include <cuda_bf16.h>
#include <stdint.h>

// Problem dims
#define NROW   16384      // B*S
#define OBSD   256
#define ACTD   32
#define CIN    288        // OBS+ACT = LAT+ACT
#define HID    2048
#define LATD   256
#define KCODE  4096

// Output layout (float32, tuple flattened in order)
#define OUT_RECON   0
#define OUT_TOK     (NROW*OBSD)
#define OUT_Q       (OUT_TOK + NROW)
#define OUT_LAT     (OUT_Q + NROW*LATD)
#define OUT_SCAL    (OUT_LAT + NROW*LATD)

// Scratch layout (floats)
#define OFF_H1      0
#define SZ_H        (NROW*HID)
#define OFF_H2      (OFF_H1 + SZ_H)
#define OFF_EMBT    (OFF_H2 + SZ_H)
#define SZ_EMBT     (LATD*KCODE)
#define OFF_ECN     (OFF_EMBT + SZ_EMBT)
#define OFF_XN      (OFF_ECN + KCODE)
#define OFF_ARGMIN  (OFF_XN + NROW)
#define OFF_ACC     (OFF_ARGMIN + 2*NROW)
#define SCRATCH_SZ  (OFF_ACC + 8)

__device__ __align__(16) float g_scratch[SCRATCH_SZ];

// ---------------------------------------------------------------------------
// helpers
// ---------------------------------------------------------------------------
__device__ __forceinline__ unsigned sortkey(float f) {
    unsigned u = __float_as_uint(f);
    return (u & 0x80000000u) ? ~u : (u | 0x80000000u);
}

__device__ __forceinline__ void cpa16(uint32_t dst, const void* src) {
    asm volatile("cp.async.cg.shared.global [%0], [%1], 16;" :: "r"(dst), "l"(src) : "memory");
}
__device__ __forceinline__ void cpa_commit() {
    asm volatile("cp.async.commit_group;" ::: "memory");
}
__device__ __forceinline__ void cpa_wait0() {
    asm volatile("cp.async.wait_group 0;" ::: "memory");
}

__device__ __forceinline__ float block_reduce_sum(float v) {
    #pragma unroll
    for (int o = 16; o > 0; o >>= 1) v += __shfl_xor_sync(0xffffffffu, v, o);
    __shared__ float sh[32];
    int lane = threadIdx.x & 31, w = threadIdx.x >> 5;
    if (lane == 0) sh[w] = v;
    __syncthreads();
    int nw = (blockDim.x + 31) >> 5;
    v = (threadIdx.x < (unsigned)nw) ? sh[threadIdx.x] : 0.0f;
    if (w == 0) {
        #pragma unroll
        for (int o = 16; o > 0; o >>= 1) v += __shfl_xor_sync(0xffffffffu, v, o);
    }
    return v;  // valid on thread 0
}

// ---------------------------------------------------------------------------
// init / norms / transpose
// ---------------------------------------------------------------------------
__global__ void init_kernel(unsigned long long* __restrict__ amin,
                            double* __restrict__ acc) {
    int i = blockIdx.x * blockDim.x + threadIdx.x;
    if (i < NROW) amin[i] = ~0ULL;
    if (i == 0) { acc[0] = 0.0; acc[1] = 0.0; }
}

__global__ void ecn_kernel(const float* __restrict__ emb, float* __restrict__ ecn) {
    int code = blockIdx.x * 8 + (threadIdx.x >> 5);
    int lane = threadIdx.x & 31;
    const float* row = emb + (size_t)code * LATD;
    float s = 0.f;
    #pragma unroll
    for (int i = 0; i < LATD / 32; i++) {
        float v = row[lane + 32 * i];
        s = fmaf(v, v, s);
    }
    #pragma unroll
    for (int o = 16; o > 0; o >>= 1) s += __shfl_xor_sync(0xffffffffu, s, o);
    if (lane == 0) ecn[code] = s;
}

__global__ void row_norms(const float* __restrict__ lat, float* __restrict__ xn) {
    int row = blockIdx.x * 8 + (threadIdx.x >> 5);
    int lane = threadIdx.x & 31;
    const float* r = lat + (size_t)row * LATD;
    float s = 0.f;
    #pragma unroll
    for (int i = 0; i < LATD / 32; i++) {
        float v = r[lane + 32 * i];
        s = fmaf(v, v, s);
    }
    #pragma unroll
    for (int o = 16; o > 0; o >>= 1) s += __shfl_xor_sync(0xffffffffu, s, o);
    if (lane == 0) xn[row] = s;
}

__global__ void transpose_emb(const float* __restrict__ emb, float* __restrict__ embT) {
    __shared__ float t[32][33];
    int j0 = blockIdx.x * 32;
    int k0 = blockIdx.y * 32;
    t[threadIdx.y][threadIdx.x] = emb[(size_t)(j0 + threadIdx.y) * LATD + k0 + threadIdx.x];
    __syncthreads();
    embT[(size_t)(k0 + threadIdx.y) * KCODE + j0 + threadIdx.x] = t[threadIdx.x][threadIdx.y];
}

// ---------------------------------------------------------------------------
// Legacy GEMM (round-7, proven): used only for the CONCAT (K=288) layers.
// ---------------------------------------------------------------------------
template <int MODE, int K, int N, bool CONCAT>
__global__ __launch_bounds__(256, 2)
void gemm128(const float* __restrict__ A, const float* __restrict__ A1,
             const float* __restrict__ W,
             const float* __restrict__ bias, float* __restrict__ C) {
    __shared__ float As[2][16][128];
    __shared__ float Bs[2][16][128];

    const int tid = threadIdx.x;
    const int tx = tid & 15;
    const int ty = tid >> 4;
    const int rowBase = blockIdx.y * 128;
    const int colBase = blockIdx.x * 128;

    const int a_r = tid >> 2;
    const int a_k = (tid & 3) * 4;
    const int b_r = tid >> 5;
    const int b_c = (tid & 31) * 4;

    const float* Aptr  = A + (size_t)(rowBase + a_r) * K + a_k;
    const float* Aptr2 = Aptr + (size_t)64 * K;
    const float* Ao1 = CONCAT ? A  + (size_t)(rowBase + a_r) * OBSD : nullptr;
    const float* Ao2 = CONCAT ? Ao1 + (size_t)64 * OBSD : nullptr;
    const float* Aa1 = CONCAT ? A1 + (size_t)(rowBase + a_r) * ACTD : nullptr;
    const float* Aa2 = CONCAT ? Aa1 + (size_t)64 * ACTD : nullptr;
    int cA = a_k;

    const float* Wptr = W + (size_t)b_r * N + colBase + b_c;

    float acc[8][8];
    #pragma unroll
    for (int i = 0; i < 8; i++)
        #pragma unroll
        for (int j = 0; j < 8; j++) acc[i][j] = 0.f;

    constexpr int nIter = K / 16;

    float4 av1, av2, bv1, bv2;
    if (CONCAT) {
        av1 = (cA < OBSD) ? *(const float4*)(Ao1 + cA) : *(const float4*)(Aa1 + (cA - OBSD));
        av2 = (cA < OBSD) ? *(const float4*)(Ao2 + cA) : *(const float4*)(Aa2 + (cA - OBSD));
    } else {
        av1 = *(const float4*)Aptr;
        av2 = *(const float4*)Aptr2;
    }
    bv1 = *(const float4*)Wptr;
    bv2 = *(const float4*)(Wptr + (size_t)8 * N);

    As[0][a_k + 0][a_r]      = av1.x; As[0][a_k + 1][a_r]      = av1.y;
    As[0][a_k + 2][a_r]      = av1.z; As[0][a_k + 3][a_r]      = av1.w;
    As[0][a_k + 0][a_r + 64] = av2.x; As[0][a_k + 1][a_r + 64] = av2.y;
    As[0][a_k + 2][a_r + 64] = av2.z; As[0][a_k + 3][a_r + 64] = av2.w;
    *(float4*)&Bs[0][b_r][b_c]     = bv1;
    *(float4*)&Bs[0][b_r + 8][b_c] = bv2;
    __syncthreads();

    for (int it = 0; it < nIter; it++) {
        const int cur = it & 1;
        const bool more = (it + 1) < nIter;

        if (more) {
            if (CONCAT) {
                cA += 16;
                av1 = (cA < OBSD) ? *(const float4*)(Ao1 + cA)
                                  : *(const float4*)(Aa1 + (cA - OBSD));
                av2 = (cA < OBSD) ? *(const float4*)(Ao2 + cA)
                                  : *(const float4*)(Aa2 + (cA - OBSD));
            } else {
                Aptr += 16; Aptr2 += 16;
                av1 = *(const float4*)Aptr;
                av2 = *(const float4*)Aptr2;
            }
            Wptr += (size_t)16 * N;
            bv1 = *(const float4*)Wptr;
            bv2 = *(const float4*)(Wptr + (size_t)8 * N);
        }

        #pragma unroll
        for (int k = 0; k < 16; k++) {
            float a[8], b[8];
            *(float4*)(a)     = *(const float4*)&As[cur][k][ty * 4];
            *(float4*)(a + 4) = *(const float4*)&As[cur][k][64 + ty * 4];
            *(float4*)(b)     = *(const float4*)&Bs[cur][k][tx * 4];
            *(float4*)(b + 4) = *(const float4*)&Bs[cur][k][64 + tx * 4];
            #pragma unroll
            for (int i = 0; i < 8; i++)
                #pragma unroll
                for (int j = 0; j < 8; j++)
                    acc[i][j] = fmaf(a[i], b[j], acc[i][j]);
        }

        if (more) {
            const int nxt = cur ^ 1;
            As[nxt][a_k + 0][a_r]      = av1.x; As[nxt][a_k + 1][a_r]      = av1.y;
            As[nxt][a_k + 2][a_r]      = av1.z; As[nxt][a_k + 3][a_r]      = av1.w;
            As[nxt][a_k + 0][a_r + 64] = av2.x; As[nxt][a_k + 1][a_r + 64] = av2.y;
            As[nxt][a_k + 2][a_r + 64] = av2.z; As[nxt][a_k + 3][a_r + 64] = av2.w;
            *(float4*)&Bs[nxt][b_r][b_c]     = bv1;
            *(float4*)&Bs[nxt][b_r + 8][b_c] = bv2;
            __syncthreads();
        }
    }

    const int cbA = colBase + tx * 4;
    const int cbB = colBase + 64 + tx * 4;
    float bs[8];
    *(float4*)(bs)     = *(const float4*)(bias + cbA);
    *(float4*)(bs + 4) = *(const float4*)(bias + cbB);
    #pragma unroll
    for (int i = 0; i < 8; i++) {
        const int row = (i < 4) ? (ty * 4 + i) : (64 + ty * 4 + (i - 4));
        float* Crow = C + (size_t)(rowBase + row) * N;
        float4 o1, o2;
        float v0 = acc[i][0] + bs[0], v1 = acc[i][1] + bs[1];
        float v2 = acc[i][2] + bs[2], v3 = acc[i][3] + bs[3];
        float v4 = acc[i][4] + bs[4], v5 = acc[i][5] + bs[5];
        float v6 = acc[i][6] + bs[6], v7 = acc[i][7] + bs[7];
        if (MODE == 0) {
            v0 = fmaxf(v0, 0.f); v1 = fmaxf(v1, 0.f);
            v2 = fmaxf(v2, 0.f); v3 = fmaxf(v3, 0.f);
            v4 = fmaxf(v4, 0.f); v5 = fmaxf(v5, 0.f);
            v6 = fmaxf(v6, 0.f); v7 = fmaxf(v7, 0.f);
        }
        o1.x = v0; o1.y = v1; o1.z = v2; o1.w = v3;
        o2.x = v4; o2.y = v5; o2.z = v6; o2.w = v7;
        *(float4*)(Crow + cbA) = o1;
        *(float4*)(Crow + cbB) = o2;
    }
}

// ---------------------------------------------------------------------------
// Pipelined GEMM: fragment double-buffering (no LDS->FFMA stalls) +
// cp.async B staging (no B prefetch regs / STS). A stays register-prefetch
// with transposed STS. 128x128x16 tiles, 256 threads, 8x8/thread, 2 CTAs/SM.
// MODE 0: relu(A*W + bias)   MODE 1: A*W + bias
// MODE 2: distance-argmin with reference fp32 rounding fl(fl(xn-2s)+ecn)
// MODE 3: MODE 1 + fused sum((C - lref)^2) into lacc
// ---------------------------------------------------------------------------
template <int MODE, int K, int N>
__global__ __launch_bounds__(256, 2)
void gemm_pipe(const float* __restrict__ A, const float* __restrict__ W,
               const float* __restrict__ bias, float* __restrict__ C,
               unsigned long long* __restrict__ amin,
               const float* __restrict__ xn,
               const float* __restrict__ lref, double* __restrict__ lacc) {
    __shared__ float As[2][16][128];
    __shared__ float Bs[2][16][128];

    const int tid = threadIdx.x;
    const int tx = tid & 15;
    const int ty = tid >> 4;
    const int rowBase = blockIdx.y * 128;
    const int colBase = blockIdx.x * 128;

    // A loader
    const int a_r = tid >> 2;
    const int a_k = (tid & 3) * 4;
    const float* Aptr = A + (size_t)(rowBase + a_r) * K + a_k;

    // B cp.async mapping: 16 threads per k-row, 8 floats (2x16B) per thread
    const int b_kr = tid >> 4;          // 0..15
    const int b_c  = (tid & 15) * 8;    // 0..120
    const float* Wc = W + (size_t)b_kr * N + colBase + b_c;
    const uint32_t bs0 = (uint32_t)__cvta_generic_to_shared(&Bs[0][b_kr][b_c]);

    float acc[8][8];
    #pragma unroll
    for (int i = 0; i < 8; i++)
        #pragma unroll
        for (int j = 0; j < 8; j++) acc[i][j] = 0.f;

    constexpr int nIter = K / 16;

    // prologue: stage tile 0 (B async, A sync)
    cpa16(bs0, Wc); cpa16(bs0 + 16, Wc + 4);
    cpa_commit();
    float4 av1 = *(const float4*)Aptr;
    float4 av2 = *(const float4*)(Aptr + (size_t)64 * K);
    As[0][a_k + 0][a_r]      = av1.x; As[0][a_k + 1][a_r]      = av1.y;
    As[0][a_k + 2][a_r]      = av1.z; As[0][a_k + 3][a_r]      = av1.w;
    As[0][a_k + 0][a_r + 64] = av2.x; As[0][a_k + 1][a_r + 64] = av2.y;
    As[0][a_k + 2][a_r + 64] = av2.z; As[0][a_k + 3][a_r + 64] = av2.w;
    cpa_wait0();
    __syncthreads();

    float af[2][8], bf[2][8];
    *(float4*)(af[0])     = *(const float4*)&As[0][0][ty * 4];
    *(float4*)(af[0] + 4) = *(const float4*)&As[0][0][64 + ty * 4];
    *(float4*)(bf[0])     = *(const float4*)&Bs[0][0][tx * 4];
    *(float4*)(bf[0] + 4) = *(const float4*)&Bs[0][0][64 + tx * 4];

    for (int it = 0; it < nIter; it++) {
        const int cur = it & 1;
        const bool more = (it + 1) < nIter;

        if (more) {
            Aptr += 16;
            av1 = *(const float4*)Aptr;
            av2 = *(const float4*)(Aptr + (size_t)64 * K);
            Wc += (size_t)16 * N;
            const uint32_t bd = bs0 + (uint32_t)(cur ^ 1) * 8192u;
            cpa16(bd, Wc); cpa16(bd + 16, Wc + 4);
            cpa_commit();
        }

        #pragma unroll
        for (int k = 0; k < 16; k++) {
            const int pb = k & 1;
            if (k < 15) {
                const int nb = pb ^ 1;
                *(float4*)(af[nb])     = *(const float4*)&As[cur][k + 1][ty * 4];
                *(float4*)(af[nb] + 4) = *(const float4*)&As[cur][k + 1][64 + ty * 4];
                *(float4*)(bf[nb])     = *(const float4*)&Bs[cur][k + 1][tx * 4];
                *(float4*)(bf[nb] + 4) = *(const float4*)&Bs[cur][k + 1][64 + tx * 4];
            }
            #pragma unroll
            for (int i = 0; i < 8; i++)
                #pragma unroll
                for (int j = 0; j < 8; j++)
                    acc[i][j] = fmaf(af[pb][i], bf[pb][j], acc[i][j]);
        }

        if (more) {
            const int nxt = cur ^ 1;
            As[nxt][a_k + 0][a_r]      = av1.x; As[nxt][a_k + 1][a_r]      = av1.y;
            As[nxt][a_k + 2][a_r]      = av1.z; As[nxt][a_k + 3][a_r]      = av1.w;
            As[nxt][a_k + 0][a_r + 64] = av2.x; As[nxt][a_k + 1][a_r + 64] = av2.y;
            As[nxt][a_k + 2][a_r + 64] = av2.z; As[nxt][a_k + 3][a_r + 64] = av2.w;
            cpa_wait0();
            __syncthreads();
            *(float4*)(af[0])     = *(const float4*)&As[nxt][0][ty * 4];
            *(float4*)(af[0] + 4) = *(const float4*)&As[nxt][0][64 + ty * 4];
            *(float4*)(bf[0])     = *(const float4*)&Bs[nxt][0][tx * 4];
            *(float4*)(bf[0] + 4) = *(const float4*)&Bs[nxt][0][64 + tx * 4];
        }
    }

    // epilogues -------------------------------------------------------------
    if (MODE == 2) {
        const int cbA = colBase + tx * 4;
        const int cbB = colBase + 64 + tx * 4;
        float ev[8];
        *(float4*)(ev)     = *(const float4*)(bias + cbA);
        *(float4*)(ev + 4) = *(const float4*)(bias + cbB);
        #pragma unroll
        for (int i = 0; i < 8; i++) {
            const int row = (i < 4) ? (ty * 4 + i) : (64 + ty * 4 + (i - 4));
            const float xr = xn[rowBase + row];
            unsigned long long best = ~0ULL;
            #pragma unroll
            for (int j = 0; j < 8; j++) {
                float t = fmaf(-2.0f, acc[i][j], xr);
                float d = t + ev[j];
                const int col = (j < 4) ? (cbA + j) : (cbB + (j - 4));
                unsigned long long p =
                    ((unsigned long long)sortkey(d) << 32) | (unsigned)col;
                best = p < best ? p : best;
            }
            #pragma unroll
            for (int o = 8; o > 0; o >>= 1) {
                unsigned long long v = __shfl_xor_sync(0xffffffffu, best, o);
                best = v < best ? v : best;
            }
            if (tx == 0)
                atomicMin(&amin[rowBase + row], best);
        }
    } else {
        const int cbA = colBase + tx * 4;
        const int cbB = colBase + 64 + tx * 4;
        float bs[8];
        *(float4*)(bs)     = *(const float4*)(bias + cbA);
        *(float4*)(bs + 4) = *(const float4*)(bias + cbB);
        float lsum = 0.f;
        #pragma unroll
        for (int i = 0; i < 8; i++) {
            const int row = (i < 4) ? (ty * 4 + i) : (64 + ty * 4 + (i - 4));
            float* Crow = C + (size_t)(rowBase + row) * N;
            float4 o1, o2;
            float v0 = acc[i][0] + bs[0], v1 = acc[i][1] + bs[1];
            float v2 = acc[i][2] + bs[2], v3 = acc[i][3] + bs[3];
            float v4 = acc[i][4] + bs[4], v5 = acc[i][5] + bs[5];
            float v6 = acc[i][6] + bs[6], v7 = acc[i][7] + bs[7];
            if (MODE == 0) {
                v0 = fmaxf(v0, 0.f); v1 = fmaxf(v1, 0.f);
                v2 = fmaxf(v2, 0.f); v3 = fmaxf(v3, 0.f);
                v4 = fmaxf(v4, 0.f); v5 = fmaxf(v5, 0.f);
                v6 = fmaxf(v6, 0.f); v7 = fmaxf(v7, 0.f);
            }
            o1.x = v0; o1.y = v1; o1.z = v2; o1.w = v3;
            o2.x = v4; o2.y = v5; o2.z = v6; o2.w = v7;
            *(float4*)(Crow + cbA) = o1;
            *(float4*)(Crow + cbB) = o2;
            if (MODE == 3) {
                const float* Rrow = lref + (size_t)(rowBase + row) * N;
                float4 r1 = *(const float4*)(Rrow + cbA);
                float4 r2 = *(const float4*)(Rrow + cbB);
                float d0 = v0 - r1.x, d1 = v1 - r1.y, d2 = v2 - r1.z, d3 = v3 - r1.w;
                float d4 = v4 - r2.x, d5 = v5 - r2.y, d6 = v6 - r2.z, d7 = v7 - r2.w;
                lsum = fmaf(d0, d0, lsum); lsum = fmaf(d1, d1, lsum);
                lsum = fmaf(d2, d2, lsum); lsum = fmaf(d3, d3, lsum);
                lsum = fmaf(d4, d4, lsum); lsum = fmaf(d5, d5, lsum);
                lsum = fmaf(d6, d6, lsum); lsum = fmaf(d7, d7, lsum);
            }
        }
        if (MODE == 3) {
            float s = block_reduce_sum(lsum);
            if (tid == 0) atomicAdd(lacc, (double)s);
        }
    }
}

// ---------------------------------------------------------------------------
// gather quantized rows, emit tokens, accumulate sum((lat - q)^2)
// ---------------------------------------------------------------------------
__global__ void gather_quant(const unsigned long long* __restrict__ amin,
                             const float* __restrict__ emb,
                             const float* __restrict__ lat,
                             float* __restrict__ out_tok,
                             float* __restrict__ out_q,
                             double* __restrict__ acc) {
    int row = blockIdx.x;
    int t = threadIdx.x;  // 256 == LATD
    unsigned idx = (unsigned)(amin[row] & 0xffffffffu);
    float q = emb[(size_t)idx * LATD + t];
    float l = lat[(size_t)row * LATD + t];
    out_q[(size_t)row * LATD + t] = q;
    float d = l - q;
    float s = block_reduce_sum(d * d);
    if (t == 0) {
        out_tok[row] = (float)idx;
        atomicAdd(&acc[0], (double)s);
    }
}

// ---------------------------------------------------------------------------
// scalars
// ---------------------------------------------------------------------------
__global__ void finalize(const double* __restrict__ acc, float* __restrict__ scal) {
    double mq = acc[0] / ((double)NROW * (double)LATD);
    double mr = acc[1] / ((double)NROW * (double)OBSD);
    scal[0] = (float)mr;
    scal[1] = (float)(0.25 * mq);
    scal[2] = (float)mq;
    scal[3] = (float)(1.25 * mq);
    scal[4] = (float)(mr + 1.25 * mq);
}

// ---------------------------------------------------------------------------
extern "C" void kernel_launch(void* const* d_in, const int* in_sizes, int n_in,
                              void* d_out, int out_size) {
    (void)in_sizes; (void)n_in; (void)out_size;
    const float* obs     = (const float*)d_in[0];
    const float* actions = (const float*)d_in[1];
    const float* enc_w1  = (const float*)d_in[2];
    const float* enc_b1  = (const float*)d_in[3];
    const float* enc_w2  = (const float*)d_in[4];
    const float* enc_b2  = (const float*)d_in[5];
    const float* enc_w3  = (const float*)d_in[6];
    const float* enc_b3  = (const float*)d_in[7];
    const float* emb     = (const float*)d_in[8];
    const float* dec_w1  = (const float*)d_in[9];
    const float* dec_b1  = (const float*)d_in[10];
    const float* dec_w2  = (const float*)d_in[11];
    const float* dec_b2  = (const float*)d_in[12];
    const float* dec_w3  = (const float*)d_in[13];
    const float* dec_b3  = (const float*)d_in[14];

    float* S = nullptr;
    cudaGetSymbolAddress((void**)&S, g_scratch);
    float* H1   = S + OFF_H1;
    float* H2   = S + OFF_H2;
    float* EMBT = S + OFF_EMBT;
    float* ECN  = S + OFF_ECN;
    float* XN   = S + OFF_XN;
    unsigned long long* AM = (unsigned long long*)(S + OFF_ARGMIN);
    double* ACC = (double*)(S + OFF_ACC);

    float* out   = (float*)d_out;
    float* recon = out + OUT_RECON;
    float* tok   = out + OUT_TOK;
    float* q     = out + OUT_Q;
    float* lat   = out + OUT_LAT;
    float* scal  = out + OUT_SCAL;

    init_kernel<<<NROW / 256, 256>>>(AM, ACC);
    ecn_kernel<<<KCODE / 8, 256>>>(emb, ECN);
    transpose_emb<<<dim3(KCODE / 32, LATD / 32), dim3(32, 32)>>>(emb, EMBT);

    // encoder
    gemm128<0, CIN, HID, true><<<dim3(HID / 128, NROW / 128), 256>>>(
        obs, actions, enc_w1, enc_b1, H1);
    gemm_pipe<0, HID, HID><<<dim3(HID / 128, NROW / 128), 256>>>(
        H1, enc_w2, enc_b2, H2, nullptr, nullptr, nullptr, nullptr);
    gemm_pipe<1, HID, LATD><<<dim3(LATD / 128, NROW / 128), 256>>>(
        H2, enc_w3, enc_b3, lat, nullptr, nullptr, nullptr, nullptr);

    // quantize
    row_norms<<<NROW / 8, 256>>>(lat, XN);
    gemm_pipe<2, LATD, KCODE><<<dim3(KCODE / 128, NROW / 128), 256>>>(
        lat, EMBT, ECN, nullptr, AM, XN, nullptr, nullptr);
    gather_quant<<<NROW, LATD>>>(AM, emb, lat, tok, q, ACC);

    // decoder
    gemm128<0, CIN, HID, true><<<dim3(HID / 128, NROW / 128), 256>>>(
        q, actions, dec_w1, dec_b1, H1);
    gemm_pipe<0, HID, HID><<<dim3(HID / 128, NROW / 128), 256>>>(
        H1, dec_w2, dec_b2, H2, nullptr, nullptr, nullptr, nullptr);
    gemm_pipe<3, HID, OBSD><<<dim3(OBSD / 128, NROW / 128), 256>>>(
        H2, dec_w3, dec_b3, recon, nullptr, nullptr, obs, &ACC[1]);

    finalize<<<1, 1>>>(ACC, scal);
}

// round 12
// speedup vs baseline: 1.2854x; 1.2854x over previous
#include <cuda_runtime.h>
#include <cuda_bf16.h>
#include <stdint.h>

// Problem dims
#define NROW   16384      // B*S
#define OBSD   256
#define ACTD   32
#define CIN    288        // OBS+ACT = LAT+ACT
#define HID    2048
#define LATD   256
#define KCODE  4096

// Output layout (float32, tuple flattened in order)
#define OUT_RECON   0
#define OUT_TOK     (NROW*OBSD)
#define OUT_Q       (OUT_TOK + NROW)
#define OUT_LAT     (OUT_Q + NROW*LATD)
#define OUT_SCAL    (OUT_LAT + NROW*LATD)

// Scratch layout (floats)
#define OFF_H1      0
#define SZ_H        (NROW*HID)
#define OFF_H2      (OFF_H1 + SZ_H)
#define OFF_EMBT    (OFF_H2 + SZ_H)
#define SZ_EMBT     (LATD*KCODE)
#define OFF_ECN     (OFF_EMBT + SZ_EMBT)
#define OFF_XN      (OFF_ECN + KCODE)
#define OFF_ARGMIN  (OFF_XN + NROW)
#define OFF_ACC     (OFF_ARGMIN + 2*NROW)
#define OFF_WHI     (OFF_ACC + 8)              // bf16 [HID][HID]
#define OFF_WLO     (OFF_WHI + (HID*HID/2))
#define SCRATCH_SZ  (OFF_WLO + (HID*HID/2))

__device__ __align__(16) float g_scratch[SCRATCH_SZ];

// ---------------------------------------------------------------------------
// helpers
// ---------------------------------------------------------------------------
__device__ __forceinline__ unsigned sortkey(float f) {
    unsigned u = __float_as_uint(f);
    return (u & 0x80000000u) ? ~u : (u | 0x80000000u);
}

__device__ __forceinline__ float block_reduce_sum(float v) {
    #pragma unroll
    for (int o = 16; o > 0; o >>= 1) v += __shfl_xor_sync(0xffffffffu, v, o);
    __shared__ float sh[32];
    int lane = threadIdx.x & 31, w = threadIdx.x >> 5;
    if (lane == 0) sh[w] = v;
    __syncthreads();
    int nw = (blockDim.x + 31) >> 5;
    v = (threadIdx.x < (unsigned)nw) ? sh[threadIdx.x] : 0.0f;
    if (w == 0) {
        #pragma unroll
        for (int o = 16; o > 0; o >>= 1) v += __shfl_xor_sync(0xffffffffu, v, o);
    }
    return v;  // valid on thread 0
}

// ---------------------------------------------------------------------------
// init / norms / transpose
// ---------------------------------------------------------------------------
__global__ void init_kernel(unsigned long long* __restrict__ amin,
                            double* __restrict__ acc) {
    int i = blockIdx.x * blockDim.x + threadIdx.x;
    if (i < NROW) amin[i] = ~0ULL;
    if (i == 0) { acc[0] = 0.0; acc[1] = 0.0; }
}

__global__ void ecn_kernel(const float* __restrict__ emb, float* __restrict__ ecn) {
    int code = blockIdx.x * 8 + (threadIdx.x >> 5);
    int lane = threadIdx.x & 31;
    const float* row = emb + (size_t)code * LATD;
    float s = 0.f;
    #pragma unroll
    for (int i = 0; i < LATD / 32; i++) {
        float v = row[lane + 32 * i];
        s = fmaf(v, v, s);
    }
    #pragma unroll
    for (int o = 16; o > 0; o >>= 1) s += __shfl_xor_sync(0xffffffffu, s, o);
    if (lane == 0) ecn[code] = s;
}

__global__ void row_norms(const float* __restrict__ lat, float* __restrict__ xn) {
    int row = blockIdx.x * 8 + (threadIdx.x >> 5);
    int lane = threadIdx.x & 31;
    const float* r = lat + (size_t)row * LATD;
    float s = 0.f;
    #pragma unroll
    for (int i = 0; i < LATD / 32; i++) {
        float v = r[lane + 32 * i];
        s = fmaf(v, v, s);
    }
    #pragma unroll
    for (int o = 16; o > 0; o >>= 1) s += __shfl_xor_sync(0xffffffffu, s, o);
    if (lane == 0) xn[row] = s;
}

__global__ void transpose_emb(const float* __restrict__ emb, float* __restrict__ embT) {
    __shared__ float t[32][33];
    int j0 = blockIdx.x * 32;
    int k0 = blockIdx.y * 32;
    t[threadIdx.y][threadIdx.x] = emb[(size_t)(j0 + threadIdx.y) * LATD + k0 + threadIdx.x];
    __syncthreads();
    embT[(size_t)(k0 + threadIdx.y) * KCODE + j0 + threadIdx.x] = t[threadIdx.x][threadIdx.y];
}

// W [K][N] fp32 -> WT hi/lo [N][K] bf16 (transposed + split)
__global__ void split_transpose_w(const float* __restrict__ W,
                                  __nv_bfloat16* __restrict__ hi,
                                  __nv_bfloat16* __restrict__ lo) {
    __shared__ float t[32][33];
    int n0 = blockIdx.x * 32;
    int k0 = blockIdx.y * 32;
    t[threadIdx.y][threadIdx.x] = W[(size_t)(k0 + threadIdx.y) * HID + n0 + threadIdx.x];
    __syncthreads();
    float v = t[threadIdx.x][threadIdx.y];   // = W[k0+tx][n0+ty]
    __nv_bfloat16 h = __float2bfloat16(v);
    __nv_bfloat16 l = __float2bfloat16(v - __bfloat162float(h));
    size_t o = (size_t)(n0 + threadIdx.y) * HID + k0 + threadIdx.x;
    hi[o] = h;
    lo[o] = l;
}

// ---------------------------------------------------------------------------
// Round-7 SIMT GEMM (proven 7071us config). All layers except dec2.
// MODE 0: relu(A*W+b)  1: A*W+b  2: dist-argmin (ref rounding)  3: 1+fused loss
// ---------------------------------------------------------------------------
template <int MODE, int K, int N, bool CONCAT>
__global__ __launch_bounds__(256, 2)
void gemm128(const float* __restrict__ A, const float* __restrict__ A1,
             const float* __restrict__ W,
             const float* __restrict__ bias, float* __restrict__ C,
             unsigned long long* __restrict__ amin,
             const float* __restrict__ xn,
             const float* __restrict__ lref, double* __restrict__ lacc) {
    __shared__ float As[2][16][128];
    __shared__ float Bs[2][16][128];

    const int tid = threadIdx.x;
    const int tx = tid & 15;
    const int ty = tid >> 4;
    const int rowBase = blockIdx.y * 128;
    const int colBase = blockIdx.x * 128;

    const int a_r = tid >> 2;
    const int a_k = (tid & 3) * 4;
    const int b_r = tid >> 5;
    const int b_c = (tid & 31) * 4;

    const float* Aptr  = A + (size_t)(rowBase + a_r) * K + a_k;
    const float* Aptr2 = Aptr + (size_t)64 * K;
    const float* Ao1 = CONCAT ? A  + (size_t)(rowBase + a_r) * OBSD : nullptr;
    const float* Ao2 = CONCAT ? Ao1 + (size_t)64 * OBSD : nullptr;
    const float* Aa1 = CONCAT ? A1 + (size_t)(rowBase + a_r) * ACTD : nullptr;
    const float* Aa2 = CONCAT ? Aa1 + (size_t)64 * ACTD : nullptr;
    int cA = a_k;

    const float* Wptr = W + (size_t)b_r * N + colBase + b_c;

    float acc[8][8];
    #pragma unroll
    for (int i = 0; i < 8; i++)
        #pragma unroll
        for (int j = 0; j < 8; j++) acc[i][j] = 0.f;

    constexpr int nIter = K / 16;

    float4 av1, av2, bv1, bv2;
    if (CONCAT) {
        av1 = (cA < OBSD) ? *(const float4*)(Ao1 + cA) : *(const float4*)(Aa1 + (cA - OBSD));
        av2 = (cA < OBSD) ? *(const float4*)(Ao2 + cA) : *(const float4*)(Aa2 + (cA - OBSD));
    } else {
        av1 = *(const float4*)Aptr;
        av2 = *(const float4*)Aptr2;
    }
    bv1 = *(const float4*)Wptr;
    bv2 = *(const float4*)(Wptr + (size_t)8 * N);

    As[0][a_k + 0][a_r]      = av1.x; As[0][a_k + 1][a_r]      = av1.y;
    As[0][a_k + 2][a_r]      = av1.z; As[0][a_k + 3][a_r]      = av1.w;
    As[0][a_k + 0][a_r + 64] = av2.x; As[0][a_k + 1][a_r + 64] = av2.y;
    As[0][a_k + 2][a_r + 64] = av2.z; As[0][a_k + 3][a_r + 64] = av2.w;
    *(float4*)&Bs[0][b_r][b_c]     = bv1;
    *(float4*)&Bs[0][b_r + 8][b_c] = bv2;
    __syncthreads();

    for (int it = 0; it < nIter; it++) {
        const int cur = it & 1;
        const bool more = (it + 1) < nIter;

        if (more) {
            if (CONCAT) {
                cA += 16;
                av1 = (cA < OBSD) ? *(const float4*)(Ao1 + cA)
                                  : *(const float4*)(Aa1 + (cA - OBSD));
                av2 = (cA < OBSD) ? *(const float4*)(Ao2 + cA)
                                  : *(const float4*)(Aa2 + (cA - OBSD));
            } else {
                Aptr += 16; Aptr2 += 16;
                av1 = *(const float4*)Aptr;
                av2 = *(const float4*)Aptr2;
            }
            Wptr += (size_t)16 * N;
            bv1 = *(const float4*)Wptr;
            bv2 = *(const float4*)(Wptr + (size_t)8 * N);
        }

        #pragma unroll
        for (int k = 0; k < 16; k++) {
            float a[8], b[8];
            *(float4*)(a)     = *(const float4*)&As[cur][k][ty * 4];
            *(float4*)(a + 4) = *(const float4*)&As[cur][k][64 + ty * 4];
            *(float4*)(b)     = *(const float4*)&Bs[cur][k][tx * 4];
            *(float4*)(b + 4) = *(const float4*)&Bs[cur][k][64 + tx * 4];
            #pragma unroll
            for (int i = 0; i < 8; i++)
                #pragma unroll
                for (int j = 0; j < 8; j++)
                    acc[i][j] = fmaf(a[i], b[j], acc[i][j]);
        }

        if (more) {
            const int nxt = cur ^ 1;
            As[nxt][a_k + 0][a_r]      = av1.x; As[nxt][a_k + 1][a_r]      = av1.y;
            As[nxt][a_k + 2][a_r]      = av1.z; As[nxt][a_k + 3][a_r]      = av1.w;
            As[nxt][a_k + 0][a_r + 64] = av2.x; As[nxt][a_k + 1][a_r + 64] = av2.y;
            As[nxt][a_k + 2][a_r + 64] = av2.z; As[nxt][a_k + 3][a_r + 64] = av2.w;
            *(float4*)&Bs[nxt][b_r][b_c]     = bv1;
            *(float4*)&Bs[nxt][b_r + 8][b_c] = bv2;
            __syncthreads();
        }
    }

    if (MODE == 2) {
        const int cbA = colBase + tx * 4;
        const int cbB = colBase + 64 + tx * 4;
        float ev[8];
        *(float4*)(ev)     = *(const float4*)(bias + cbA);
        *(float4*)(ev + 4) = *(const float4*)(bias + cbB);
        #pragma unroll
        for (int i = 0; i < 8; i++) {
            const int row = (i < 4) ? (ty * 4 + i) : (64 + ty * 4 + (i - 4));
            const float xr = xn[rowBase + row];
            unsigned long long best = ~0ULL;
            #pragma unroll
            for (int j = 0; j < 8; j++) {
                float t = fmaf(-2.0f, acc[i][j], xr);
                float d = t + ev[j];
                const int col = (j < 4) ? (cbA + j) : (cbB + (j - 4));
                unsigned long long p =
                    ((unsigned long long)sortkey(d) << 32) | (unsigned)col;
                best = p < best ? p : best;
            }
            #pragma unroll
            for (int o = 8; o > 0; o >>= 1) {
                unsigned long long v = __shfl_xor_sync(0xffffffffu, best, o);
                best = v < best ? v : best;
            }
            if (tx == 0)
                atomicMin(&amin[rowBase + row], best);
        }
    } else {
        const int cbA = colBase + tx * 4;
        const int cbB = colBase + 64 + tx * 4;
        float bs[8];
        *(float4*)(bs)     = *(const float4*)(bias + cbA);
        *(float4*)(bs + 4) = *(const float4*)(bias + cbB);
        float lsum = 0.f;
        #pragma unroll
        for (int i = 0; i < 8; i++) {
            const int row = (i < 4) ? (ty * 4 + i) : (64 + ty * 4 + (i - 4));
            float* Crow = C + (size_t)(rowBase + row) * N;
            float4 o1, o2;
            float v0 = acc[i][0] + bs[0], v1 = acc[i][1] + bs[1];
            float v2 = acc[i][2] + bs[2], v3 = acc[i][3] + bs[3];
            float v4 = acc[i][4] + bs[4], v5 = acc[i][5] + bs[5];
            float v6 = acc[i][6] + bs[6], v7 = acc[i][7] + bs[7];
            if (MODE == 0) {
                v0 = fmaxf(v0, 0.f); v1 = fmaxf(v1, 0.f);
                v2 = fmaxf(v2, 0.f); v3 = fmaxf(v3, 0.f);
                v4 = fmaxf(v4, 0.f); v5 = fmaxf(v5, 0.f);
                v6 = fmaxf(v6, 0.f); v7 = fmaxf(v7, 0.f);
            }
            o1.x = v0; o1.y = v1; o1.z = v2; o1.w = v3;
            o2.x = v4; o2.y = v5; o2.z = v6; o2.w = v7;
            *(float4*)(Crow + cbA) = o1;
            *(float4*)(Crow + cbB) = o2;
            if (MODE == 3) {
                const float* Rrow = lref + (size_t)(rowBase + row) * N;
                float4 r1 = *(const float4*)(Rrow + cbA);
                float4 r2 = *(const float4*)(Rrow + cbB);
                float d0 = v0 - r1.x, d1 = v1 - r1.y, d2 = v2 - r1.z, d3 = v3 - r1.w;
                float d4 = v4 - r2.x, d5 = v5 - r2.y, d6 = v6 - r2.z, d7 = v7 - r2.w;
                lsum = fmaf(d0, d0, lsum); lsum = fmaf(d1, d1, lsum);
                lsum = fmaf(d2, d2, lsum); lsum = fmaf(d3, d3, lsum);
                lsum = fmaf(d4, d4, lsum); lsum = fmaf(d5, d5, lsum);
                lsum = fmaf(d6, d6, lsum); lsum = fmaf(d7, d7, lsum);
            }
        }
        if (MODE == 3) {
            float s = block_reduce_sum(lsum);
            if (tid == 0) atomicAdd(lacc, (double)s);
        }
    }
}

// ---------------------------------------------------------------------------
// dec2 via mma.sync.m16n8k16 bf16 (baseline PTX -> compiles for sm_103).
// C = relu(A@W + b), split: Ahi*Whi + Ahi*Wlo + Alo*Whi, fp32 accum.
// 128x128 CTA tile, 8 warps (2x4), warp tile 64x32 (4 mtiles x 4 ntiles).
// K chunks of 64 (4 ksteps). Smem rows padded to 72 u16 (144B) -> fragment
// LDS hits banks g*4+t (all distinct) = conflict-free.
// ---------------------------------------------------------------------------
#define MMP 72                        // smem pitch in u16
#define MM_TILE (128 * MMP)           // u16 per buffer
#define MM_SMEM_BYTES (4 * MM_TILE * 2)

__device__ __forceinline__ void hmma16816(float* d, const uint32_t* a,
                                          const uint32_t* b) {
    asm volatile(
        "mma.sync.aligned.m16n8k16.row.col.f32.bf16.bf16.f32 "
        "{%0,%1,%2,%3}, {%4,%5,%6,%7}, {%8,%9}, {%0,%1,%2,%3};"
        : "+f"(d[0]), "+f"(d[1]), "+f"(d[2]), "+f"(d[3])
        : "r"(a[0]), "r"(a[1]), "r"(a[2]), "r"(a[3]), "r"(b[0]), "r"(b[1]));
}

__device__ __forceinline__ unsigned short bfu(float x) {
    __nv_bfloat16 h = __float2bfloat16(x);
    return reinterpret_cast<unsigned short&>(h);
}

__global__ __launch_bounds__(256, 2)
void mma_dec2(const float* __restrict__ A,
              const __nv_bfloat16* __restrict__ WhiT,
              const __nv_bfloat16* __restrict__ WloT,
              const float* __restrict__ bias,
              float* __restrict__ C) {
    extern __shared__ __align__(16) unsigned short sm[];
    unsigned short* Ahi = sm;
    unsigned short* Alo = sm + MM_TILE;
    unsigned short* Bhi = sm + 2 * MM_TILE;
    unsigned short* Blo = sm + 3 * MM_TILE;

    const int tid = threadIdx.x;
    const int wid = tid >> 5;
    const int lane = tid & 31;
    const int g = lane >> 2;
    const int t = lane & 3;
    const int wm = wid & 1;           // 0..1 -> m offset 64*wm
    const int wn = wid >> 1;          // 0..3 -> n offset 32*wn
    const int rowBase = blockIdx.y * 128;
    const int colBase = blockIdx.x * 128;

    float acc[4][4][4];
    #pragma unroll
    for (int m = 0; m < 4; m++)
        #pragma unroll
        for (int n = 0; n < 4; n++)
            #pragma unroll
            for (int r = 0; r < 4; r++) acc[m][n][r] = 0.f;

    for (int ch = 0; ch < HID / 64; ch++) {
        const int kb = ch * 64;
        __syncthreads();   // previous compute done before overwrite

        // stage A: 128 rows x 64 fp32 -> bf16 hi/lo (16 float4 per row)
        #pragma unroll
        for (int it = 0; it < 8; it++) {
            int f = tid + 256 * it;
            int r = f >> 4, c4 = f & 15;
            float4 v = *(const float4*)(A + (size_t)(rowBase + r) * HID + kb + c4 * 4);
            unsigned short h0 = bfu(v.x), h1 = bfu(v.y), h2 = bfu(v.z), h3 = bfu(v.w);
            float hf0 = __bfloat162float(__ushort_as_bfloat16(h0));
            float hf1 = __bfloat162float(__ushort_as_bfloat16(h1));
            float hf2 = __bfloat162float(__ushort_as_bfloat16(h2));
            float hf3 = __bfloat162float(__ushort_as_bfloat16(h3));
            unsigned short l0 = bfu(v.x - hf0), l1 = bfu(v.y - hf1);
            unsigned short l2 = bfu(v.z - hf2), l3 = bfu(v.w - hf3);
            int idx = r * MMP + c4 * 4;
            *(uint32_t*)&Ahi[idx]     = (uint32_t)h0 | ((uint32_t)h1 << 16);
            *(uint32_t*)&Ahi[idx + 2] = (uint32_t)h2 | ((uint32_t)h3 << 16);
            *(uint32_t*)&Alo[idx]     = (uint32_t)l0 | ((uint32_t)l1 << 16);
            *(uint32_t*)&Alo[idx + 2] = (uint32_t)l2 | ((uint32_t)l3 << 16);
        }
        // stage B: 128 n-rows x 64 bf16 each (8 uint4 per row)
        #pragma unroll
        for (int it = 0; it < 4; it++) {
            int f = tid + 256 * it;
            int r = f >> 3, c = f & 7;
            const __nv_bfloat16* ph = WhiT + (size_t)(colBase + r) * HID + kb + c * 8;
            const __nv_bfloat16* pl = WloT + (size_t)(colBase + r) * HID + kb + c * 8;
            *(uint4*)&Bhi[r * MMP + c * 8] = *(const uint4*)ph;
            *(uint4*)&Blo[r * MMP + c * 8] = *(const uint4*)pl;
        }
        __syncthreads();

        #pragma unroll
        for (int ks = 0; ks < 4; ks++) {
            const int kc = ks * 16;
            uint32_t af[4][4], bh[4][2], bl[4][2];
            // a_hi fragments
            #pragma unroll
            for (int m = 0; m < 4; m++) {
                int r0 = wm * 64 + m * 16 + g;
                int c0 = kc + t * 2;
                af[m][0] = *(const uint32_t*)&Ahi[r0 * MMP + c0];
                af[m][1] = *(const uint32_t*)&Ahi[(r0 + 8) * MMP + c0];
                af[m][2] = *(const uint32_t*)&Ahi[r0 * MMP + c0 + 8];
                af[m][3] = *(const uint32_t*)&Ahi[(r0 + 8) * MMP + c0 + 8];
            }
            // b_hi fragments
            #pragma unroll
            for (int n = 0; n < 4; n++) {
                int n0 = wn * 32 + n * 8 + g;
                int c0 = kc + t * 2;
                bh[n][0] = *(const uint32_t*)&Bhi[n0 * MMP + c0];
                bh[n][1] = *(const uint32_t*)&Bhi[n0 * MMP + c0 + 8];
            }
            // hi*hi
            #pragma unroll
            for (int m = 0; m < 4; m++)
                #pragma unroll
                for (int n = 0; n < 4; n++)
                    hmma16816(acc[m][n], af[m], bh[n]);
            // b_lo, hi*lo
            #pragma unroll
            for (int n = 0; n < 4; n++) {
                int n0 = wn * 32 + n * 8 + g;
                int c0 = kc + t * 2;
                bl[n][0] = *(const uint32_t*)&Blo[n0 * MMP + c0];
                bl[n][1] = *(const uint32_t*)&Blo[n0 * MMP + c0 + 8];
            }
            #pragma unroll
            for (int m = 0; m < 4; m++)
                #pragma unroll
                for (int n = 0; n < 4; n++)
                    hmma16816(acc[m][n], af[m], bl[n]);
            // a_lo, lo*hi
            #pragma unroll
            for (int m = 0; m < 4; m++) {
                int r0 = wm * 64 + m * 16 + g;
                int c0 = kc + t * 2;
                af[m][0] = *(const uint32_t*)&Alo[r0 * MMP + c0];
                af[m][1] = *(const uint32_t*)&Alo[(r0 + 8) * MMP + c0];
                af[m][2] = *(const uint32_t*)&Alo[r0 * MMP + c0 + 8];
                af[m][3] = *(const uint32_t*)&Alo[(r0 + 8) * MMP + c0 + 8];
            }
            #pragma unroll
            for (int m = 0; m < 4; m++)
                #pragma unroll
                for (int n = 0; n < 4; n++)
                    hmma16816(acc[m][n], af[m], bh[n]);
        }
    }

    // epilogue: bias + relu
    #pragma unroll
    for (int m = 0; m < 4; m++) {
        int row = rowBase + wm * 64 + m * 16 + g;
        #pragma unroll
        for (int n = 0; n < 4; n++) {
            int col = colBase + wn * 32 + n * 8 + t * 2;
            float b0 = bias[col], b1 = bias[col + 1];
            float2 o0, o1;
            o0.x = fmaxf(acc[m][n][0] + b0, 0.f);
            o0.y = fmaxf(acc[m][n][1] + b1, 0.f);
            o1.x = fmaxf(acc[m][n][2] + b0, 0.f);
            o1.y = fmaxf(acc[m][n][3] + b1, 0.f);
            *(float2*)(C + (size_t)row * HID + col) = o0;
            *(float2*)(C + (size_t)(row + 8) * HID + col) = o1;
        }
    }
}

// ---------------------------------------------------------------------------
// gather quantized rows, emit tokens, accumulate sum((lat - q)^2)
// ---------------------------------------------------------------------------
__global__ void gather_quant(const unsigned long long* __restrict__ amin,
                             const float* __restrict__ emb,
                             const float* __restrict__ lat,
                             float* __restrict__ out_tok,
                             float* __restrict__ out_q,
                             double* __restrict__ acc) {
    int row = blockIdx.x;
    int t = threadIdx.x;  // 256 == LATD
    unsigned idx = (unsigned)(amin[row] & 0xffffffffu);
    float q = emb[(size_t)idx * LATD + t];
    float l = lat[(size_t)row * LATD + t];
    out_q[(size_t)row * LATD + t] = q;
    float d = l - q;
    float s = block_reduce_sum(d * d);
    if (t == 0) {
        out_tok[row] = (float)idx;
        atomicAdd(&acc[0], (double)s);
    }
}

// ---------------------------------------------------------------------------
// scalars
// ---------------------------------------------------------------------------
__global__ void finalize(const double* __restrict__ acc, float* __restrict__ scal) {
    double mq = acc[0] / ((double)NROW * (double)LATD);
    double mr = acc[1] / ((double)NROW * (double)OBSD);
    scal[0] = (float)mr;
    scal[1] = (float)(0.25 * mq);
    scal[2] = (float)mq;
    scal[3] = (float)(1.25 * mq);
    scal[4] = (float)(mr + 1.25 * mq);
}

// ---------------------------------------------------------------------------
extern "C" void kernel_launch(void* const* d_in, const int* in_sizes, int n_in,
                              void* d_out, int out_size) {
    (void)in_sizes; (void)n_in; (void)out_size;
    const float* obs     = (const float*)d_in[0];
    const float* actions = (const float*)d_in[1];
    const float* enc_w1  = (const float*)d_in[2];
    const float* enc_b1  = (const float*)d_in[3];
    const float* enc_w2  = (const float*)d_in[4];
    const float* enc_b2  = (const float*)d_in[5];
    const float* enc_w3  = (const float*)d_in[6];
    const float* enc_b3  = (const float*)d_in[7];
    const float* emb     = (const float*)d_in[8];
    const float* dec_w1  = (const float*)d_in[9];
    const float* dec_b1  = (const float*)d_in[10];
    const float* dec_w2  = (const float*)d_in[11];
    const float* dec_b2  = (const float*)d_in[12];
    const float* dec_w3  = (const float*)d_in[13];
    const float* dec_b3  = (const float*)d_in[14];

    float* S = nullptr;
    cudaGetSymbolAddress((void**)&S, g_scratch);
    float* H1   = S + OFF_H1;
    float* H2   = S + OFF_H2;
    float* EMBT = S + OFF_EMBT;
    float* ECN  = S + OFF_ECN;
    float* XN   = S + OFF_XN;
    unsigned long long* AM = (unsigned long long*)(S + OFF_ARGMIN);
    double* ACC = (double*)(S + OFF_ACC);
    __nv_bfloat16* WHI = (__nv_bfloat16*)(S + OFF_WHI);
    __nv_bfloat16* WLO = (__nv_bfloat16*)(S + OFF_WLO);

    float* out   = (float*)d_out;
    float* recon = out + OUT_RECON;
    float* tok   = out + OUT_TOK;
    float* q     = out + OUT_Q;
    float* lat   = out + OUT_LAT;
    float* scal  = out + OUT_SCAL;

    cudaFuncSetAttribute(mma_dec2, cudaFuncAttributeMaxDynamicSharedMemorySize,
                         MM_SMEM_BYTES);

    init_kernel<<<NROW / 256, 256>>>(AM, ACC);
    ecn_kernel<<<KCODE / 8, 256>>>(emb, ECN);
    transpose_emb<<<dim3(KCODE / 32, LATD / 32), dim3(32, 32)>>>(emb, EMBT);
    split_transpose_w<<<dim3(HID / 32, HID / 32), dim3(32, 32)>>>(dec_w2, WHI, WLO);

    // encoder (untouched fp32 path -> tokens/latents bit-identical to R7)
    gemm128<0, CIN, HID, true><<<dim3(HID / 128, NROW / 128), 256>>>(
        obs, actions, enc_w1, enc_b1, H1, nullptr, nullptr, nullptr, nullptr);
    gemm128<0, HID, HID, false><<<dim3(HID / 128, NROW / 128), 256>>>(
        H1, nullptr, enc_w2, enc_b2, H2, nullptr, nullptr, nullptr, nullptr);
    gemm128<1, HID, LATD, false><<<dim3(LATD / 128, NROW / 128), 256>>>(
        H2, nullptr, enc_w3, enc_b3, lat, nullptr, nullptr, nullptr, nullptr);

    // quantize
    row_norms<<<NROW / 8, 256>>>(lat, XN);
    gemm128<2, LATD, KCODE, false><<<dim3(KCODE / 128, NROW / 128), 256>>>(
        lat, nullptr, EMBT, ECN, nullptr, AM, XN, nullptr, nullptr);
    gather_quant<<<NROW, LATD>>>(AM, emb, lat, tok, q, ACC);

    // decoder
    gemm128<0, CIN, HID, true><<<dim3(HID / 128, NROW / 128), 256>>>(
        q, actions, dec_w1, dec_b1, H1, nullptr, nullptr, nullptr, nullptr);
    mma_dec2<<<dim3(HID / 128, NROW / 128), 256, MM_SMEM_BYTES>>>(
        H1, WHI, WLO, dec_b2, H2);
    gemm128<3, HID, OBSD, false><<<dim3(OBSD / 128, NROW / 128), 256>>>(
        H2, nullptr, dec_w3, dec_b3, recon, nullptr, nullptr, obs, &ACC[1]);

    finalize<<<1, 1>>>(ACC, scal);
}

// round 16
// speedup vs baseline: 1.3690x; 1.0650x over previous
#include <cuda_runtime.h>
#include <cuda_bf16.h>
#include <stdint.h>

// Problem dims
#define NROW   16384      // B*S
#define OBSD   256
#define ACTD   32
#define CIN    288        // OBS+ACT = LAT+ACT
#define HID    2048
#define LATD   256
#define KCODE  4096

// Output layout (float32, tuple flattened in order)
#define OUT_RECON   0
#define OUT_TOK     (NROW*OBSD)
#define OUT_Q       (OUT_TOK + NROW)
#define OUT_LAT     (OUT_Q + NROW*LATD)
#define OUT_SCAL    (OUT_LAT + NROW*LATD)

// Scratch layout (floats)
#define OFF_H1      0
#define SZ_H        (NROW*HID)
#define OFF_H2      (OFF_H1 + SZ_H)
#define OFF_EMBT    (OFF_H2 + SZ_H)
#define SZ_EMBT     (LATD*KCODE)
#define OFF_ECN     (OFF_EMBT + SZ_EMBT)
#define OFF_XN      (OFF_ECN + KCODE)
#define OFF_ARGMIN  (OFF_XN + NROW)
#define OFF_ACC     (OFF_ARGMIN + 2*NROW)
#define OFF_W2HI    (OFF_ACC + 8)                      // bf16 [HID][HID]
#define OFF_W2LO    (OFF_W2HI + (HID*HID/2))
#define OFF_W1HI    (OFF_W2LO + (HID*HID/2))           // bf16 [HID][CIN]
#define OFF_W1LO    (OFF_W1HI + (HID*CIN/2))
#define OFF_W3HI    (OFF_W1LO + (HID*CIN/2))           // bf16 [OBSD][HID]
#define OFF_W3LO    (OFF_W3HI + (OBSD*HID/2))
#define SCRATCH_SZ  (OFF_W3LO + (OBSD*HID/2))

__device__ __align__(16) float g_scratch[SCRATCH_SZ];

// ---------------------------------------------------------------------------
// helpers
// ---------------------------------------------------------------------------
__device__ __forceinline__ unsigned sortkey(float f) {
    unsigned u = __float_as_uint(f);
    return (u & 0x80000000u) ? ~u : (u | 0x80000000u);
}

__device__ __forceinline__ float block_reduce_sum(float v) {
    #pragma unroll
    for (int o = 16; o > 0; o >>= 1) v += __shfl_xor_sync(0xffffffffu, v, o);
    __shared__ float sh[32];
    int lane = threadIdx.x & 31, w = threadIdx.x >> 5;
    if (lane == 0) sh[w] = v;
    __syncthreads();
    int nw = (blockDim.x + 31) >> 5;
    v = (threadIdx.x < (unsigned)nw) ? sh[threadIdx.x] : 0.0f;
    if (w == 0) {
        #pragma unroll
        for (int o = 16; o > 0; o >>= 1) v += __shfl_xor_sync(0xffffffffu, v, o);
    }
    return v;  // valid on thread 0
}

// ---------------------------------------------------------------------------
// init / norms / transpose
// ---------------------------------------------------------------------------
__global__ void init_kernel(unsigned long long* __restrict__ amin,
                            double* __restrict__ acc) {
    int i = blockIdx.x * blockDim.x + threadIdx.x;
    if (i < NROW) amin[i] = ~0ULL;
    if (i == 0) { acc[0] = 0.0; acc[1] = 0.0; }
}

__global__ void ecn_kernel(const float* __restrict__ emb, float* __restrict__ ecn) {
    int code = blockIdx.x * 8 + (threadIdx.x >> 5);
    int lane = threadIdx.x & 31;
    const float* row = emb + (size_t)code * LATD;
    float s = 0.f;
    #pragma unroll
    for (int i = 0; i < LATD / 32; i++) {
        float v = row[lane + 32 * i];
        s = fmaf(v, v, s);
    }
    #pragma unroll
    for (int o = 16; o > 0; o >>= 1) s += __shfl_xor_sync(0xffffffffu, s, o);
    if (lane == 0) ecn[code] = s;
}

__global__ void row_norms(const float* __restrict__ lat, float* __restrict__ xn) {
    int row = blockIdx.x * 8 + (threadIdx.x >> 5);
    int lane = threadIdx.x & 31;
    const float* r = lat + (size_t)row * LATD;
    float s = 0.f;
    #pragma unroll
    for (int i = 0; i < LATD / 32; i++) {
        float v = r[lane + 32 * i];
        s = fmaf(v, v, s);
    }
    #pragma unroll
    for (int o = 16; o > 0; o >>= 1) s += __shfl_xor_sync(0xffffffffu, s, o);
    if (lane == 0) xn[row] = s;
}

__global__ void transpose_emb(const float* __restrict__ emb, float* __restrict__ embT) {
    __shared__ float t[32][33];
    int j0 = blockIdx.x * 32;
    int k0 = blockIdx.y * 32;
    t[threadIdx.y][threadIdx.x] = emb[(size_t)(j0 + threadIdx.y) * LATD + k0 + threadIdx.x];
    __syncthreads();
    embT[(size_t)(k0 + threadIdx.y) * KCODE + j0 + threadIdx.x] = t[threadIdx.x][threadIdx.y];
}

// W [K][N] fp32 -> WT hi/lo [N][K] bf16 (transposed + split)
template <int K, int N>
__global__ void split_transpose_w(const float* __restrict__ W,
                                  __nv_bfloat16* __restrict__ hi,
                                  __nv_bfloat16* __restrict__ lo) {
    __shared__ float t[32][33];
    int n0 = blockIdx.x * 32;
    int k0 = blockIdx.y * 32;
    t[threadIdx.y][threadIdx.x] = W[(size_t)(k0 + threadIdx.y) * N + n0 + threadIdx.x];
    __syncthreads();
    float v = t[threadIdx.x][threadIdx.y];   // = W[k0+tx][n0+ty]
    __nv_bfloat16 h = __float2bfloat16(v);
    __nv_bfloat16 l = __float2bfloat16(v - __bfloat162float(h));
    size_t o = (size_t)(n0 + threadIdx.y) * K + k0 + threadIdx.x;
    hi[o] = h;
    lo[o] = l;
}

// ---------------------------------------------------------------------------
// Round-7 SIMT GEMM (proven): encoder + distance layers (fp32-exact path).
// MODE 0: relu(A*W+b)  1: A*W+b  2: dist-argmin (ref rounding)
// ---------------------------------------------------------------------------
template <int MODE, int K, int N, bool CONCAT>
__global__ __launch_bounds__(256, 2)
void gemm128(const float* __restrict__ A, const float* __restrict__ A1,
             const float* __restrict__ W,
             const float* __restrict__ bias, float* __restrict__ C,
             unsigned long long* __restrict__ amin,
             const float* __restrict__ xn) {
    __shared__ float As[2][16][128];
    __shared__ float Bs[2][16][128];

    const int tid = threadIdx.x;
    const int tx = tid & 15;
    const int ty = tid >> 4;
    const int rowBase = blockIdx.y * 128;
    const int colBase = blockIdx.x * 128;

    const int a_r = tid >> 2;
    const int a_k = (tid & 3) * 4;
    const int b_r = tid >> 5;
    const int b_c = (tid & 31) * 4;

    const float* Aptr  = A + (size_t)(rowBase + a_r) * K + a_k;
    const float* Aptr2 = Aptr + (size_t)64 * K;
    const float* Ao1 = CONCAT ? A  + (size_t)(rowBase + a_r) * OBSD : nullptr;
    const float* Ao2 = CONCAT ? Ao1 + (size_t)64 * OBSD : nullptr;
    const float* Aa1 = CONCAT ? A1 + (size_t)(rowBase + a_r) * ACTD : nullptr;
    const float* Aa2 = CONCAT ? Aa1 + (size_t)64 * ACTD : nullptr;
    int cA = a_k;

    const float* Wptr = W + (size_t)b_r * N + colBase + b_c;

    float acc[8][8];
    #pragma unroll
    for (int i = 0; i < 8; i++)
        #pragma unroll
        for (int j = 0; j < 8; j++) acc[i][j] = 0.f;

    constexpr int nIter = K / 16;

    float4 av1, av2, bv1, bv2;
    if (CONCAT) {
        av1 = (cA < OBSD) ? *(const float4*)(Ao1 + cA) : *(const float4*)(Aa1 + (cA - OBSD));
        av2 = (cA < OBSD) ? *(const float4*)(Ao2 + cA) : *(const float4*)(Aa2 + (cA - OBSD));
    } else {
        av1 = *(const float4*)Aptr;
        av2 = *(const float4*)Aptr2;
    }
    bv1 = *(const float4*)Wptr;
    bv2 = *(const float4*)(Wptr + (size_t)8 * N);

    As[0][a_k + 0][a_r]      = av1.x; As[0][a_k + 1][a_r]      = av1.y;
    As[0][a_k + 2][a_r]      = av1.z; As[0][a_k + 3][a_r]      = av1.w;
    As[0][a_k + 0][a_r + 64] = av2.x; As[0][a_k + 1][a_r + 64] = av2.y;
    As[0][a_k + 2][a_r + 64] = av2.z; As[0][a_k + 3][a_r + 64] = av2.w;
    *(float4*)&Bs[0][b_r][b_c]     = bv1;
    *(float4*)&Bs[0][b_r + 8][b_c] = bv2;
    __syncthreads();

    for (int it = 0; it < nIter; it++) {
        const int cur = it & 1;
        const bool more = (it + 1) < nIter;

        if (more) {
            if (CONCAT) {
                cA += 16;
                av1 = (cA < OBSD) ? *(const float4*)(Ao1 + cA)
                                  : *(const float4*)(Aa1 + (cA - OBSD));
                av2 = (cA < OBSD) ? *(const float4*)(Ao2 + cA)
                                  : *(const float4*)(Aa2 + (cA - OBSD));
            } else {
                Aptr += 16; Aptr2 += 16;
                av1 = *(const float4*)Aptr;
                av2 = *(const float4*)Aptr2;
            }
            Wptr += (size_t)16 * N;
            bv1 = *(const float4*)Wptr;
            bv2 = *(const float4*)(Wptr + (size_t)8 * N);
        }

        #pragma unroll
        for (int k = 0; k < 16; k++) {
            float a[8], b[8];
            *(float4*)(a)     = *(const float4*)&As[cur][k][ty * 4];
            *(float4*)(a + 4) = *(const float4*)&As[cur][k][64 + ty * 4];
            *(float4*)(b)     = *(const float4*)&Bs[cur][k][tx * 4];
            *(float4*)(b + 4) = *(const float4*)&Bs[cur][k][64 + tx * 4];
            #pragma unroll
            for (int i = 0; i < 8; i++)
                #pragma unroll
                for (int j = 0; j < 8; j++)
                    acc[i][j] = fmaf(a[i], b[j], acc[i][j]);
        }

        if (more) {
            const int nxt = cur ^ 1;
            As[nxt][a_k + 0][a_r]      = av1.x; As[nxt][a_k + 1][a_r]      = av1.y;
            As[nxt][a_k + 2][a_r]      = av1.z; As[nxt][a_k + 3][a_r]      = av1.w;
            As[nxt][a_k + 0][a_r + 64] = av2.x; As[nxt][a_k + 1][a_r + 64] = av2.y;
            As[nxt][a_k + 2][a_r + 64] = av2.z; As[nxt][a_k + 3][a_r + 64] = av2.w;
            *(float4*)&Bs[nxt][b_r][b_c]     = bv1;
            *(float4*)&Bs[nxt][b_r + 8][b_c] = bv2;
            __syncthreads();
        }
    }

    if (MODE == 2) {
        const int cbA = colBase + tx * 4;
        const int cbB = colBase + 64 + tx * 4;
        float ev[8];
        *(float4*)(ev)     = *(const float4*)(bias + cbA);
        *(float4*)(ev + 4) = *(const float4*)(bias + cbB);
        #pragma unroll
        for (int i = 0; i < 8; i++) {
            const int row = (i < 4) ? (ty * 4 + i) : (64 + ty * 4 + (i - 4));
            const float xr = xn[rowBase + row];
            unsigned long long best = ~0ULL;
            #pragma unroll
            for (int j = 0; j < 8; j++) {
                float t = fmaf(-2.0f, acc[i][j], xr);
                float d = t + ev[j];
                const int col = (j < 4) ? (cbA + j) : (cbB + (j - 4));
                unsigned long long p =
                    ((unsigned long long)sortkey(d) << 32) | (unsigned)col;
                best = p < best ? p : best;
            }
            #pragma unroll
            for (int o = 8; o > 0; o >>= 1) {
                unsigned long long v = __shfl_xor_sync(0xffffffffu, best, o);
                best = v < best ? v : best;
            }
            if (tx == 0)
                atomicMin(&amin[rowBase + row], best);
        }
    } else {
        const int cbA = colBase + tx * 4;
        const int cbB = colBase + 64 + tx * 4;
        float bs[8];
        *(float4*)(bs)     = *(const float4*)(bias + cbA);
        *(float4*)(bs + 4) = *(const float4*)(bias + cbB);
        #pragma unroll
        for (int i = 0; i < 8; i++) {
            const int row = (i < 4) ? (ty * 4 + i) : (64 + ty * 4 + (i - 4));
            float* Crow = C + (size_t)(rowBase + row) * N;
            float4 o1, o2;
            float v0 = acc[i][0] + bs[0], v1 = acc[i][1] + bs[1];
            float v2 = acc[i][2] + bs[2], v3 = acc[i][3] + bs[3];
            float v4 = acc[i][4] + bs[4], v5 = acc[i][5] + bs[5];
            float v6 = acc[i][6] + bs[6], v7 = acc[i][7] + bs[7];
            if (MODE == 0) {
                v0 = fmaxf(v0, 0.f); v1 = fmaxf(v1, 0.f);
                v2 = fmaxf(v2, 0.f); v3 = fmaxf(v3, 0.f);
                v4 = fmaxf(v4, 0.f); v5 = fmaxf(v5, 0.f);
                v6 = fmaxf(v6, 0.f); v7 = fmaxf(v7, 0.f);
            }
            o1.x = v0; o1.y = v1; o1.z = v2; o1.w = v3;
            o2.x = v4; o2.y = v5; o2.z = v6; o2.w = v7;
            *(float4*)(Crow + cbA) = o1;
            *(float4*)(Crow + cbB) = o2;
        }
    }
}

// ---------------------------------------------------------------------------
// Generalized HMMA split GEMM (proven on dec2 @ R12): C = act(A@W + b).
// Split: Ahi*Whi + Ahi*Wlo + Alo*Whi, fp32 accum. 128x128 CTA tile, 8 warps.
// Template: MODE 0 relu / 1 none / 3 none+fused sum((C-lref)^2) into lacc.
// CH = K-chunk (64 or 32; 256 % CH == 0 so CONCAT chunks never straddle).
// Smem pitch CH+8 u16 -> conflict-free fragment loads.
// ---------------------------------------------------------------------------
__device__ __forceinline__ void hmma16816(float* d, const uint32_t* a,
                                          const uint32_t* b) {
    asm volatile(
        "mma.sync.aligned.m16n8k16.row.col.f32.bf16.bf16.f32 "
        "{%0,%1,%2,%3}, {%4,%5,%6,%7}, {%8,%9}, {%0,%1,%2,%3};"
        : "+f"(d[0]), "+f"(d[1]), "+f"(d[2]), "+f"(d[3])
        : "r"(a[0]), "r"(a[1]), "r"(a[2]), "r"(a[3]), "r"(b[0]), "r"(b[1]));
}

__device__ __forceinline__ unsigned short bfu(float x) {
    __nv_bfloat16 h = __float2bfloat16(x);
    return reinterpret_cast<unsigned short&>(h);
}

template <int MODE, int K, int N, int CH, bool CONCAT>
__global__ __launch_bounds__(256, 2)
void mma_gemm(const float* __restrict__ A, const float* __restrict__ A1,
              const __nv_bfloat16* __restrict__ WhiT,
              const __nv_bfloat16* __restrict__ WloT,
              const float* __restrict__ bias, float* __restrict__ C,
              const float* __restrict__ lref, double* __restrict__ lacc) {
    constexpr int P = CH + 8;            // smem pitch in u16
    constexpr int TILE = 128 * P;
    extern __shared__ __align__(16) unsigned short sm[];
    unsigned short* Ahi = sm;
    unsigned short* Alo = sm + TILE;
    unsigned short* Bhi = sm + 2 * TILE;
    unsigned short* Blo = sm + 3 * TILE;

    const int tid = threadIdx.x;
    const int wid = tid >> 5;
    const int lane = tid & 31;
    const int g = lane >> 2;
    const int t = lane & 3;
    const int wm = wid & 1;
    const int wn = wid >> 1;
    const int rowBase = blockIdx.y * 128;
    const int colBase = blockIdx.x * 128;

    float acc[4][4][4];
    #pragma unroll
    for (int m = 0; m < 4; m++)
        #pragma unroll
        for (int n = 0; n < 4; n++)
            #pragma unroll
            for (int r = 0; r < 4; r++) acc[m][n][r] = 0.f;

    for (int ch = 0; ch < K / CH; ch++) {
        const int kb = ch * CH;
        __syncthreads();   // previous compute done before overwrite

        // stage A: 128 rows x CH fp32 -> bf16 hi/lo (CH/4 float4 per row)
        #pragma unroll
        for (int it = 0; it < CH / 8; it++) {
            int f = tid + 256 * it;
            int r = f / (CH / 4), c4 = f % (CH / 4);
            const float* src;
            if (CONCAT) {
                // chunk wholly in q (kb < OBSD) or actions (kb >= OBSD)
                src = (kb < OBSD)
                    ? A  + (size_t)(rowBase + r) * OBSD + kb + c4 * 4
                    : A1 + (size_t)(rowBase + r) * ACTD + (kb - OBSD) + c4 * 4;
            } else {
                src = A + (size_t)(rowBase + r) * K + kb + c4 * 4;
            }
            float4 v = *(const float4*)src;
            unsigned short h0 = bfu(v.x), h1 = bfu(v.y), h2 = bfu(v.z), h3 = bfu(v.w);
            float hf0 = __bfloat162float(__ushort_as_bfloat16(h0));
            float hf1 = __bfloat162float(__ushort_as_bfloat16(h1));
            float hf2 = __bfloat162float(__ushort_as_bfloat16(h2));
            float hf3 = __bfloat162float(__ushort_as_bfloat16(h3));
            unsigned short l0 = bfu(v.x - hf0), l1 = bfu(v.y - hf1);
            unsigned short l2 = bfu(v.z - hf2), l3 = bfu(v.w - hf3);
            int idx = r * P + c4 * 4;
            *(uint32_t*)&Ahi[idx]     = (uint32_t)h0 | ((uint32_t)h1 << 16);
            *(uint32_t*)&Ahi[idx + 2] = (uint32_t)h2 | ((uint32_t)h3 << 16);
            *(uint32_t*)&Alo[idx]     = (uint32_t)l0 | ((uint32_t)l1 << 16);
            *(uint32_t*)&Alo[idx + 2] = (uint32_t)l2 | ((uint32_t)l3 << 16);
        }
        // stage B: 128 n-rows x CH bf16 (CH/8 uint4 per row)
        #pragma unroll
        for (int it = 0; it < CH / 16; it++) {
            int f = tid + 256 * it;
            int r = f / (CH / 8), c = f % (CH / 8);
            const __nv_bfloat16* ph = WhiT + (size_t)(colBase + r) * K + kb + c * 8;
            const __nv_bfloat16* pl = WloT + (size_t)(colBase + r) * K + kb + c * 8;
            *(uint4*)&Bhi[r * P + c * 8] = *(const uint4*)ph;
            *(uint4*)&Blo[r * P + c * 8] = *(const uint4*)pl;
        }
        __syncthreads();

        #pragma unroll
        for (int ks = 0; ks < CH / 16; ks++) {
            const int kc = ks * 16;
            uint32_t af[4][4], bh[4][2], bl[4][2];
            #pragma unroll
            for (int m = 0; m < 4; m++) {
                int r0 = wm * 64 + m * 16 + g;
                int c0 = kc + t * 2;
                af[m][0] = *(const uint32_t*)&Ahi[r0 * P + c0];
                af[m][1] = *(const uint32_t*)&Ahi[(r0 + 8) * P + c0];
                af[m][2] = *(const uint32_t*)&Ahi[r0 * P + c0 + 8];
                af[m][3] = *(const uint32_t*)&Ahi[(r0 + 8) * P + c0 + 8];
            }
            #pragma unroll
            for (int n = 0; n < 4; n++) {
                int n0 = wn * 32 + n * 8 + g;
                int c0 = kc + t * 2;
                bh[n][0] = *(const uint32_t*)&Bhi[n0 * P + c0];
                bh[n][1] = *(const uint32_t*)&Bhi[n0 * P + c0 + 8];
            }
            #pragma unroll
            for (int m = 0; m < 4; m++)
                #pragma unroll
                for (int n = 0; n < 4; n++)
                    hmma16816(acc[m][n], af[m], bh[n]);
            #pragma unroll
            for (int n = 0; n < 4; n++) {
                int n0 = wn * 32 + n * 8 + g;
                int c0 = kc + t * 2;
                bl[n][0] = *(const uint32_t*)&Blo[n0 * P + c0];
                bl[n][1] = *(const uint32_t*)&Blo[n0 * P + c0 + 8];
            }
            #pragma unroll
            for (int m = 0; m < 4; m++)
                #pragma unroll
                for (int n = 0; n < 4; n++)
                    hmma16816(acc[m][n], af[m], bl[n]);
            #pragma unroll
            for (int m = 0; m < 4; m++) {
                int r0 = wm * 64 + m * 16 + g;
                int c0 = kc + t * 2;
                af[m][0] = *(const uint32_t*)&Alo[r0 * P + c0];
                af[m][1] = *(const uint32_t*)&Alo[(r0 + 8) * P + c0];
                af[m][2] = *(const uint32_t*)&Alo[r0 * P + c0 + 8];
                af[m][3] = *(const uint32_t*)&Alo[(r0 + 8) * P + c0 + 8];
            }
            #pragma unroll
            for (int m = 0; m < 4; m++)
                #pragma unroll
                for (int n = 0; n < 4; n++)
                    hmma16816(acc[m][n], af[m], bh[n]);
        }
    }

    // epilogue: bias (+relu MODE 0) (+fused loss MODE 3)
    float lsum = 0.f;
    #pragma unroll
    for (int m = 0; m < 4; m++) {
        int row = rowBase + wm * 64 + m * 16 + g;
        #pragma unroll
        for (int n = 0; n < 4; n++) {
            int col = colBase + wn * 32 + n * 8 + t * 2;
            float b0 = bias[col], b1 = bias[col + 1];
            float v0 = acc[m][n][0] + b0, v1 = acc[m][n][1] + b1;
            float v2 = acc[m][n][2] + b0, v3 = acc[m][n][3] + b1;
            if (MODE == 0) {
                v0 = fmaxf(v0, 0.f); v1 = fmaxf(v1, 0.f);
                v2 = fmaxf(v2, 0.f); v3 = fmaxf(v3, 0.f);
            }
            float2 o0, o1;
            o0.x = v0; o0.y = v1; o1.x = v2; o1.y = v3;
            *(float2*)(C + (size_t)row * N + col) = o0;
            *(float2*)(C + (size_t)(row + 8) * N + col) = o1;
            if (MODE == 3) {
                const float* R0 = lref + (size_t)row * N + col;
                const float* R1 = lref + (size_t)(row + 8) * N + col;
                float d0 = v0 - R0[0], d1 = v1 - R0[1];
                float d2 = v2 - R1[0], d3 = v3 - R1[1];
                lsum = fmaf(d0, d0, lsum); lsum = fmaf(d1, d1, lsum);
                lsum = fmaf(d2, d2, lsum); lsum = fmaf(d3, d3, lsum);
            }
        }
    }
    if (MODE == 3) {
        float s = block_reduce_sum(lsum);
        if (tid == 0) atomicAdd(lacc, (double)s);
    }
}

// ---------------------------------------------------------------------------
// gather quantized rows, emit tokens, accumulate sum((lat - q)^2)
// ---------------------------------------------------------------------------
__global__ void gather_quant(const unsigned long long* __restrict__ amin,
                             const float* __restrict__ emb,
                             const float* __restrict__ lat,
                             float* __restrict__ out_tok,
                             float* __restrict__ out_q,
                             double* __restrict__ acc) {
    int row = blockIdx.x;
    int t = threadIdx.x;  // 256 == LATD
    unsigned idx = (unsigned)(amin[row] & 0xffffffffu);
    float q = emb[(size_t)idx * LATD + t];
    float l = lat[(size_t)row * LATD + t];
    out_q[(size_t)row * LATD + t] = q;
    float d = l - q;
    float s = block_reduce_sum(d * d);
    if (t == 0) {
        out_tok[row] = (float)idx;
        atomicAdd(&acc[0], (double)s);
    }
}

// ---------------------------------------------------------------------------
// scalars
// ---------------------------------------------------------------------------
__global__ void finalize(const double* __restrict__ acc, float* __restrict__ scal) {
    double mq = acc[0] / ((double)NROW * (double)LATD);
    double mr = acc[1] / ((double)NROW * (double)OBSD);
    scal[0] = (float)mr;
    scal[1] = (float)(0.25 * mq);
    scal[2] = (float)mq;
    scal[3] = (float)(1.25 * mq);
    scal[4] = (float)(mr + 1.25 * mq);
}

// ---------------------------------------------------------------------------
extern "C" void kernel_launch(void* const* d_in, const int* in_sizes, int n_in,
                              void* d_out, int out_size) {
    (void)in_sizes; (void)n_in; (void)out_size;
    const float* obs     = (const float*)d_in[0];
    const float* actions = (const float*)d_in[1];
    const float* enc_w1  = (const float*)d_in[2];
    const float* enc_b1  = (const float*)d_in[3];
    const float* enc_w2  = (const float*)d_in[4];
    const float* enc_b2  = (const float*)d_in[5];
    const float* enc_w3  = (const float*)d_in[6];
    const float* enc_b3  = (const float*)d_in[7];
    const float* emb     = (const float*)d_in[8];
    const float* dec_w1  = (const float*)d_in[9];
    const float* dec_b1  = (const float*)d_in[10];
    const float* dec_w2  = (const float*)d_in[11];
    const float* dec_b2  = (const float*)d_in[12];
    const float* dec_w3  = (const float*)d_in[13];
    const float* dec_b3  = (const float*)d_in[14];

    float* S = nullptr;
    cudaGetSymbolAddress((void**)&S, g_scratch);
    float* H1   = S + OFF_H1;
    float* H2   = S + OFF_H2;
    float* EMBT = S + OFF_EMBT;
    float* ECN  = S + OFF_ECN;
    float* XN   = S + OFF_XN;
    unsigned long long* AM = (unsigned long long*)(S + OFF_ARGMIN);
    double* ACC = (double*)(S + OFF_ACC);
    __nv_bfloat16* W2HI = (__nv_bfloat16*)(S + OFF_W2HI);
    __nv_bfloat16* W2LO = (__nv_bfloat16*)(S + OFF_W2LO);
    __nv_bfloat16* W1HI = (__nv_bfloat16*)(S + OFF_W1HI);
    __nv_bfloat16* W1LO = (__nv_bfloat16*)(S + OFF_W1LO);
    __nv_bfloat16* W3HI = (__nv_bfloat16*)(S + OFF_W3HI);
    __nv_bfloat16* W3LO = (__nv_bfloat16*)(S + OFF_W3LO);

    float* out   = (float*)d_out;
    float* recon = out + OUT_RECON;
    float* tok   = out + OUT_TOK;
    float* q     = out + OUT_Q;
    float* lat   = out + OUT_LAT;
    float* scal  = out + OUT_SCAL;

    // smem sizes: CH=64 -> 4*128*72*2 = 73728 B ; CH=32 -> 4*128*40*2 = 40960 B
    cudaFuncSetAttribute(mma_gemm<0, HID, HID, 64, false>,
                         cudaFuncAttributeMaxDynamicSharedMemorySize, 73728);
    cudaFuncSetAttribute(mma_gemm<0, CIN, HID, 32, true>,
                         cudaFuncAttributeMaxDynamicSharedMemorySize, 40960);
    cudaFuncSetAttribute(mma_gemm<3, HID, OBSD, 64, false>,
                         cudaFuncAttributeMaxDynamicSharedMemorySize, 73728);

    init_kernel<<<NROW / 256, 256>>>(AM, ACC);
    ecn_kernel<<<KCODE / 8, 256>>>(emb, ECN);
    transpose_emb<<<dim3(KCODE / 32, LATD / 32), dim3(32, 32)>>>(emb, EMBT);
    split_transpose_w<CIN, HID><<<dim3(HID / 32, CIN / 32), dim3(32, 32)>>>(dec_w1, W1HI, W1LO);
    split_transpose_w<HID, HID><<<dim3(HID / 32, HID / 32), dim3(32, 32)>>>(dec_w2, W2HI, W2LO);
    split_transpose_w<HID, OBSD><<<dim3(OBSD / 32, HID / 32), dim3(32, 32)>>>(dec_w3, W3HI, W3LO);

    // encoder (untouched fp32 path -> tokens/latents bit-identical to R7)
    gemm128<0, CIN, HID, true><<<dim3(HID / 128, NROW / 128), 256>>>(
        obs, actions, enc_w1, enc_b1, H1, nullptr, nullptr);
    gemm128<0, HID, HID, false><<<dim3(HID / 128, NROW / 128), 256>>>(
        H1, nullptr, enc_w2, enc_b2, H2, nullptr, nullptr);
    gemm128<1, HID, LATD, false><<<dim3(LATD / 128, NROW / 128), 256>>>(
        H2, nullptr, enc_w3, enc_b3, lat, nullptr, nullptr);

    // quantize (fp32-exact, reference rounding chain)
    row_norms<<<NROW / 8, 256>>>(lat, XN);
    gemm128<2, LATD, KCODE, false><<<dim3(KCODE / 128, NROW / 128), 256>>>(
        lat, nullptr, EMBT, ECN, nullptr, AM, XN);
    gather_quant<<<NROW, LATD>>>(AM, emb, lat, tok, q, ACC);

    // decoder: all three layers HMMA bf16x2-split (recon-only error budget)
    mma_gemm<0, CIN, HID, 32, true><<<dim3(HID / 128, NROW / 128), 256, 40960>>>(
        q, actions, W1HI, W1LO, dec_b1, H1, nullptr, nullptr);
    mma_gemm<0, HID, HID, 64, false><<<dim3(HID / 128, NROW / 128), 256, 73728>>>(
        H1, nullptr, W2HI, W2LO, dec_b2, H2, nullptr, nullptr);
    mma_gemm<3, HID, OBSD, 64, false><<<dim3(OBSD / 128, NROW / 128), 256, 73728>>>(
        H2, nullptr, W3HI, W3LO, dec_b3, recon, obs, &ACC[1]);

    finalize<<<1, 1>>>(ACC, scal);
}